// round 1
// baseline (speedup 1.0000x reference)
#include <cuda_runtime.h>
#include <cstdint>

#define BB 128
#define TT 512
#define HH 512
#define D2 1024
#define NOUT 64
#define VN 16
#define DACT 10

// scratch (device globals; no allocation in kernel_launch)
__device__ float g_h[(size_t)BB * TT * D2];   // 268 MB: relu(out) [b][t][d]
__device__ float g_s[2][(size_t)BB * TT];     // per-direction logit partials

__device__ __forceinline__ float fex2(float x) {
    float y; asm("ex2.approx.f32 %0, %1;" : "=f"(y) : "f"(x)); return y;
}
__device__ __forceinline__ float frcp(float x) {
    float y; asm("rcp.approx.f32 %0, %1;" : "=f"(y) : "f"(x)); return y;
}
// sigmoid(x) = 1/(1+2^(-x*log2e))
__device__ __forceinline__ float fsig(float x) {
    return frcp(1.0f + fex2(-1.4426950408889634f * x));
}
// tanh(x) = 1 - 2/(1+2^(2x*log2e))
__device__ __forceinline__ float ftnh(float x) {
    return fmaf(-2.0f, frcp(1.0f + fex2(2.8853900817779268f * x)), 1.0f);
}

// -------- scan kernel: one block = (batch b, direction dir), 512 threads = h --------
// smem layout (floats): ts[2*T] | vidx[T] (as int) | table[VN*H*3] | swarp[16*T]
extern __shared__ float s_mem[];

__global__ void __launch_bounds__(512) scan_kernel(
    const float* __restrict__ x,   // (B,T,3)
    const float* __restrict__ emb, // (16,10)
    const float* __restrict__ Wf, const float* __restrict__ bfw,
    const float* __restrict__ Wb, const float* __restrict__ bbw,
    const float* __restrict__ Mu)  // (2H,1)
{
    const int b = blockIdx.x;
    const int dir = blockIdx.y;
    const int h = threadIdx.x;

    float* ts    = s_mem;                  // 2*T
    int*   vv    = (int*)(s_mem + 2 * TT); // T
    float* table = s_mem + 3 * TT;         // VN*H*3
    float* swarp = table + VN * HH * 3;    // 16*T

    const float* W    = dir ? Wb : Wf;
    const float* bias = dir ? bbw : bfw;

    // load x row for this batch into smem
    for (int t = h; t < TT; t += 512) {
        const float* xp = x + ((size_t)b * TT + t) * 3;
        ts[2 * t]     = xp[0];
        ts[2 * t + 1] = xp[1];
        vv[t]         = (int)xp[2];
    }

    // per-thread weights: ts part (e=0,1) for the 3 gates (cols h, 512+h, 1024+h)
    const int ch_z = h, ch_f = HH + h, ch_o = 2 * HH + h;
    float wz0 = W[ch_z],         wz1 = W[1536 + ch_z];
    float wf0 = W[ch_f],         wf1 = W[1536 + ch_f];
    float wo0 = W[ch_o],         wo1 = W[1536 + ch_o];

    // embedding-part weights (e=2..11)
    float wk0[DACT], wk1[DACT], wk2[DACT];
#pragma unroll
    for (int k = 0; k < DACT; k++) {
        wk0[k] = W[(2 + k) * 1536 + ch_z];
        wk1[k] = W[(2 + k) * 1536 + ch_f];
        wk2[k] = W[(2 + k) * 1536 + ch_o];
    }
    const float bz = bias[ch_z], bfv = bias[ch_f], bo = bias[ch_o];

    // build table[v][h][g] = bias_g + emb[v] . W_act_g   (bias folded in)
    for (int v = 0; v < VN; v++) {
        float az = bz, af = bfv, ao = bo;
#pragma unroll
        for (int k = 0; k < DACT; k++) {
            float e = emb[v * DACT + k];  // uniform broadcast, L1-hit
            az = fmaf(e, wk0[k], az);
            af = fmaf(e, wk1[k], af);
            ao = fmaf(e, wk2[k], ao);
        }
        float* tp = table + ((size_t)v * HH + h) * 3;  // stride-3 -> conflict-free
        tp[0] = az; tp[1] = af; tp[2] = ao;
    }
    const float mu = Mu[dir * HH + h];
    __syncthreads();

    const int lane = h & 31;
    const int wid  = h >> 5;
    float c = 0.0f;
    float* hout = g_h + (size_t)b * TT * D2 + (size_t)dir * HH + h;

    for (int i = 0; i < TT; i++) {
        const int t = dir ? (TT - 1 - i) : i;
        const float t0 = ts[2 * t];
        const float t1 = ts[2 * t + 1];
        const int   v  = vv[t];
        const float* tp = table + ((size_t)v * HH + h) * 3;
        float az = fmaf(t0, wz0, fmaf(t1, wz1, tp[0]));
        float af = fmaf(t0, wf0, fmaf(t1, wf1, tp[1]));
        float ao = fmaf(t0, wo0, fmaf(t1, wo1, tp[2]));
        float z = ftnh(az);
        float f = fsig(af);
        float o = fsig(ao);
        c = fmaf(f, c - z, z);             // f*c + (1-f)*z
        float hr = fmaxf(o * c, 0.0f);     // relu(out)
        hout[(size_t)t * D2] = hr;

        // warp-reduce hr*mu -> per-warp partial logit (deterministic, no atomics)
        float p = hr * mu;
        p += __shfl_xor_sync(0xffffffffu, p, 16);
        p += __shfl_xor_sync(0xffffffffu, p, 8);
        p += __shfl_xor_sync(0xffffffffu, p, 4);
        p += __shfl_xor_sync(0xffffffffu, p, 2);
        p += __shfl_xor_sync(0xffffffffu, p, 1);
        if (lane == 0) swarp[wid * TT + t] = p;
    }
    __syncthreads();

    // reduce 16 warp partials per t, write per-direction logits
    {
        float s = 0.0f;
#pragma unroll
        for (int w = 0; w < 16; w++) s += swarp[w * TT + h];
        g_s[dir][(size_t)b * TT + h] = s;
    }
}

// -------- finalize: softmax over T, context, relu, GEMV with W_out --------
__global__ void __launch_bounds__(1024) finalize_kernel(
    const float* __restrict__ W_out,  // (64, 1024)
    const float* __restrict__ b_out,  // (64,)
    float* __restrict__ out)          // (B, 64)
{
    __shared__ float a_sm[TT];
    __shared__ float red[32];
    __shared__ float ctx[D2];
    __shared__ float pm[1024];

    const int b = blockIdx.x;
    const int tid = threadIdx.x;
    const int lane = tid & 31;
    const int wid = tid >> 5;

    // logits
    float s = (tid < TT) ? (g_s[0][(size_t)b * TT + tid] + g_s[1][(size_t)b * TT + tid])
                         : -1e30f;
    // block max
    float m = s;
#pragma unroll
    for (int o = 16; o; o >>= 1) m = fmaxf(m, __shfl_xor_sync(0xffffffffu, m, o));
    if (lane == 0) red[wid] = m;
    __syncthreads();
    if (wid == 0) {
        float v2 = red[lane];
#pragma unroll
        for (int o = 16; o; o >>= 1) v2 = fmaxf(v2, __shfl_xor_sync(0xffffffffu, v2, o));
        if (lane == 0) red[0] = v2;
    }
    __syncthreads();
    m = red[0];

    float e = (tid < TT) ? fex2(1.4426950408889634f * (s - m)) : 0.0f;
    float su = e;
#pragma unroll
    for (int o = 16; o; o >>= 1) su += __shfl_xor_sync(0xffffffffu, su, o);
    __syncthreads();  // everyone done reading red[0]
    if (lane == 0) red[wid] = su;
    __syncthreads();
    if (wid == 0) {
        float v2 = red[lane];
#pragma unroll
        for (int o = 16; o; o >>= 1) v2 += __shfl_xor_sync(0xffffffffu, v2, o);
        if (lane == 0) red[0] = v2;
    }
    __syncthreads();
    const float Ssum = red[0];
    if (tid < TT) a_sm[tid] = e / Ssum;
    __syncthreads();

    // context[b][d] = sum_t a[t] * h[b][t][d]   (coalesced over d)
    const int d = tid;
    const float* hp = g_h + (size_t)b * TT * D2 + d;
    float a0 = 0.f, a1 = 0.f, a2 = 0.f, a3 = 0.f;
#pragma unroll 4
    for (int t = 0; t < TT; t += 4) {
        a0 = fmaf(a_sm[t],     hp[(size_t)(t)     * D2], a0);
        a1 = fmaf(a_sm[t + 1], hp[(size_t)(t + 1) * D2], a1);
        a2 = fmaf(a_sm[t + 2], hp[(size_t)(t + 2) * D2], a2);
        a3 = fmaf(a_sm[t + 3], hp[(size_t)(t + 3) * D2], a3);
    }
    ctx[d] = fmaxf((a0 + a1) + (a2 + a3), 0.0f);
    __syncthreads();

    // out[b][o] = b_out[o] + ctx . W_out[o]  (split over 16 chunks of 64)
    const int o = tid & 63;
    const int ch = tid >> 6;
    const float* wrow = W_out + (size_t)o * D2 + ch * 64;
    const float* cpt  = ctx + ch * 64;
    float acc = 0.0f;
#pragma unroll
    for (int i = 0; i < 64; i++) acc = fmaf(cpt[i], wrow[i], acc);
    pm[ch * 64 + o] = acc;
    __syncthreads();
    if (tid < 64) {
        float r = b_out[tid];
#pragma unroll
        for (int k = 0; k < 16; k++) r += pm[k * 64 + tid];
        out[(size_t)b * NOUT + tid] = r;
    }
}

extern "C" void kernel_launch(void* const* d_in, const int* in_sizes, int n_in,
                              void* d_out, int out_size) {
    const float* x     = (const float*)d_in[0];
    const float* emb   = (const float*)d_in[1];
    const float* Wf    = (const float*)d_in[2];
    const float* bf    = (const float*)d_in[3];
    const float* Wb    = (const float*)d_in[4];
    const float* bb    = (const float*)d_in[5];
    const float* Mu    = (const float*)d_in[6];
    const float* W_out = (const float*)d_in[7];
    const float* b_out = (const float*)d_in[8];
    float* out = (float*)d_out;

    // smem: (2T + T + VN*H*3 + 16T) floats = 34304 * 4 = 137216 bytes
    const int smem_bytes = (3 * TT + VN * HH * 3 + 16 * TT) * (int)sizeof(float);
    cudaFuncSetAttribute((const void*)scan_kernel,
                         cudaFuncAttributeMaxDynamicSharedMemorySize, smem_bytes);

    scan_kernel<<<dim3(BB, 2), 512, smem_bytes>>>(x, emb, Wf, bf, Wb, bb, Mu);
    finalize_kernel<<<BB, 1024>>>(W_out, b_out, out);
}

// round 2
// speedup vs baseline: 1.7795x; 1.7795x over previous
#include <cuda_runtime.h>
#include <cstdint>

#define BB 128
#define TT 512
#define HH 512
#define D2 1024
#define NOUT 64
#define VN 16
#define DACT 10

// device scratch (no allocations allowed)
__device__ float g_h[(size_t)BB * TT * D2];        // 268 MB relu(out) [b][t][d]
__device__ float g_wp[(size_t)BB * 32 * TT];       // warp logit partials [b*32+uw][t]
__device__ float g_attn[(size_t)BB * TT];          // softmax weights
__device__ float g_ctx[(size_t)BB * D2];           // relu(context)

__device__ __forceinline__ float fex2(float x) {
    float y; asm("ex2.approx.f32 %0, %1;" : "=f"(y) : "f"(x)); return y;
}
__device__ __forceinline__ float ftanh_a(float x) {
    float y; asm("tanh.approx.f32 %0, %1;" : "=f"(y) : "f"(x)); return y;
}
// sigmoid(x) = 0.5*tanh(x/2) + 0.5   (1 MUFU)
__device__ __forceinline__ float fsig_a(float x) {
    return fmaf(ftanh_a(0.5f * x), 0.5f, 0.5f);
}

// ---------------- K1: fused gate-GEMM + fo_pool scan ----------------
// block = (b, unit) ; unit = dir*2 + half ; 256 threads = h in [half*256, half*256+256)
// smem: tzf float2[VN*256] | ts2 float2[TT] | to float[VN*256] | vvp int[TT] | buf float[8*544]
extern __shared__ float s_raw[];

__global__ void __launch_bounds__(256) scan_kernel(
    const float* __restrict__ x,   // (B,T,3)
    const float* __restrict__ emb, // (16,10)
    const float* __restrict__ Wf, const float* __restrict__ bfw,
    const float* __restrict__ Wb, const float* __restrict__ bbw,
    const float* __restrict__ Mu)  // (2H,1)
{
    const int b    = blockIdx.x;
    const int unit = blockIdx.y;
    const int dir  = unit >> 1;
    const int half = unit & 1;
    const int tid  = threadIdx.x;
    const int h    = half * 256 + tid;

    float2* tzf = (float2*)s_raw;                     // VN*256 float2 (32KB)
    float2* ts2 = tzf + VN * 256;                     // TT float2 (4KB)
    float*  to  = (float*)(ts2 + TT);                 // VN*256 (16KB)
    int*    vvp = (int*)(to + VN * 256);              // TT (2KB)
    float*  buf = (float*)(vvp + TT);                 // 8*544 (17.4KB)

    const float* W    = dir ? Wb : Wf;
    const float* bias = dir ? bbw : bfw;

    // stage x row into smem
    for (int t = tid; t < TT; t += 256) {
        const float* xp = x + ((size_t)b * TT + t) * 3;
        ts2[t] = make_float2(xp[0], xp[1]);
        vvp[t] = ((int)xp[2]) * 256;
    }

    const int ch_z = h, ch_f = HH + h, ch_o = 2 * HH + h;
    const float wz0 = W[ch_z], wz1 = W[1536 + ch_z];
    const float wf0 = W[ch_f], wf1 = W[1536 + ch_f];
    const float wo0 = W[ch_o], wo1 = W[1536 + ch_o];

    // table build, one gate at a time (keeps live regs low)
    {
        float wk[DACT];
        const float bz = bias[ch_z];
#pragma unroll
        for (int k = 0; k < DACT; k++) wk[k] = W[(2 + k) * 1536 + ch_z];
        for (int v = 0; v < VN; v++) {
            float a = bz;
#pragma unroll
            for (int k = 0; k < DACT; k++) a = fmaf(emb[v * DACT + k], wk[k], a);
            ((float*)tzf)[(v * 256 + tid) * 2] = a;
        }
        const float bfv = bias[ch_f];
#pragma unroll
        for (int k = 0; k < DACT; k++) wk[k] = W[(2 + k) * 1536 + ch_f];
        for (int v = 0; v < VN; v++) {
            float a = bfv;
#pragma unroll
            for (int k = 0; k < DACT; k++) a = fmaf(emb[v * DACT + k], wk[k], a);
            ((float*)tzf)[(v * 256 + tid) * 2 + 1] = a;
        }
        const float bo = bias[ch_o];
#pragma unroll
        for (int k = 0; k < DACT; k++) wk[k] = W[(2 + k) * 1536 + ch_o];
        for (int v = 0; v < VN; v++) {
            float a = bo;
#pragma unroll
            for (int k = 0; k < DACT; k++) a = fmaf(emb[v * DACT + k], wk[k], a);
            to[v * 256 + tid] = a;
        }
    }
    const int d = dir * HH + h;
    const float mu = Mu[d];
    __syncthreads();

    const int lane = tid & 31;
    const int wid  = tid >> 5;
    float* bufw = buf + wid * 544;           // 32 x 17 padded tile
    const int rstep = dir ? -D2 : D2;

    float c = 0.0f;
    float* hp = g_h + ((size_t)b * TT + (dir ? TT - 1 : 0)) * D2 + d;
    float* wp_out = g_wp + ((size_t)(b * 4 + unit) * 8 + wid) * TT;

    for (int ch = 0; ch < TT / 16; ch++) {
#pragma unroll
        for (int j = 0; j < 16; j++) {
            const int i = ch * 16 + j;
            const int t = dir ? (TT - 1 - i) : i;
            const float2 tt = ts2[t];
            const int off = vvp[t];
            const float2 zf = tzf[off + tid];
            const float aob = to[off + tid];
            float az = fmaf(tt.x, wz0, fmaf(tt.y, wz1, zf.x));
            float af = fmaf(tt.x, wf0, fmaf(tt.y, wf1, zf.y));
            float ao = fmaf(tt.x, wo0, fmaf(tt.y, wo1, aob));
            float z = ftanh_a(az);
            float f = fsig_a(af);
            float o = fsig_a(ao);
            c = fmaf(f, c - z, z);            // f*c + (1-f)*z
            float hr = fmaxf(o * c, 0.0f);
            *hp = hr; hp += rstep;
            bufw[lane * 17 + j] = hr * mu;
        }
        __syncwarp();
        // transpose-reduce: per t_local, sum 32 lanes' products
        {
            const int tl = lane & 15, hf = lane >> 4;
            float p = 0.0f;
#pragma unroll
            for (int s = 0; s < 16; s++) p += bufw[(hf * 16 + s) * 17 + tl];
            p += __shfl_xor_sync(0xffffffffu, p, 16);
            if (hf == 0) {
                const int i = ch * 16 + tl;
                const int tg = dir ? (TT - 1 - i) : i;
                wp_out[tg] = p;
            }
        }
        __syncwarp();
    }
}

// ---------------- K2: reduce warp partials -> softmax over T ----------------
__global__ void __launch_bounds__(512) softmax_kernel()
{
    __shared__ float red[16];
    const int b = blockIdx.x;
    const int t = threadIdx.x;
    const int lane = t & 31, wid = t >> 5;

    const float* wp = g_wp + (size_t)b * 32 * TT + t;
    float s = 0.0f;
#pragma unroll
    for (int uw = 0; uw < 32; uw++) s += wp[(size_t)uw * TT];

    // block max
    float m = s;
#pragma unroll
    for (int o = 16; o; o >>= 1) m = fmaxf(m, __shfl_xor_sync(0xffffffffu, m, o));
    if (lane == 0) red[wid] = m;
    __syncthreads();
    if (wid == 0) {
        float v = (lane < 16) ? red[lane] : -1e30f;
#pragma unroll
        for (int o = 16; o; o >>= 1) v = fmaxf(v, __shfl_xor_sync(0xffffffffu, v, o));
        if (lane == 0) red[0] = v;
    }
    __syncthreads();
    m = red[0];
    __syncthreads();

    float e = fex2(1.4426950408889634f * (s - m));
    float su = e;
#pragma unroll
    for (int o = 16; o; o >>= 1) su += __shfl_xor_sync(0xffffffffu, su, o);
    if (lane == 0) red[wid] = su;
    __syncthreads();
    if (wid == 0) {
        float v = (lane < 16) ? red[lane] : 0.0f;
#pragma unroll
        for (int o = 16; o; o >>= 1) v += __shfl_xor_sync(0xffffffffu, v, o);
        if (lane == 0) red[0] = v;
    }
    __syncthreads();
    g_attn[(size_t)b * TT + t] = e / red[0];
}

// ---------------- K3: context = attn-weighted sum over T ----------------
__global__ void __launch_bounds__(512) ctx_kernel()
{
    __shared__ float a_sm[TT];
    const int b = blockIdx.x;
    const int dh = blockIdx.y;
    const int tid = threadIdx.x;

    a_sm[tid] = g_attn[(size_t)b * TT + tid];
    __syncthreads();

    const int d = dh * 512 + tid;
    const float* hp = g_h + (size_t)b * TT * D2 + d;
    float a0 = 0.f, a1 = 0.f, a2 = 0.f, a3 = 0.f;
    float a4 = 0.f, a5 = 0.f, a6 = 0.f, a7 = 0.f;
#pragma unroll 4
    for (int t = 0; t < TT; t += 8) {
        a0 = fmaf(a_sm[t + 0], hp[(size_t)(t + 0) * D2], a0);
        a1 = fmaf(a_sm[t + 1], hp[(size_t)(t + 1) * D2], a1);
        a2 = fmaf(a_sm[t + 2], hp[(size_t)(t + 2) * D2], a2);
        a3 = fmaf(a_sm[t + 3], hp[(size_t)(t + 3) * D2], a3);
        a4 = fmaf(a_sm[t + 4], hp[(size_t)(t + 4) * D2], a4);
        a5 = fmaf(a_sm[t + 5], hp[(size_t)(t + 5) * D2], a5);
        a6 = fmaf(a_sm[t + 6], hp[(size_t)(t + 6) * D2], a6);
        a7 = fmaf(a_sm[t + 7], hp[(size_t)(t + 7) * D2], a7);
    }
    float sum = ((a0 + a1) + (a2 + a3)) + ((a4 + a5) + (a6 + a7));
    g_ctx[(size_t)b * D2 + d] = fmaxf(sum, 0.0f);
}

// ---------------- K4: out = ctx @ W_out^T + b_out ----------------
__global__ void __launch_bounds__(512) out_kernel(
    const float* __restrict__ W_out, const float* __restrict__ b_out,
    float* __restrict__ out)
{
    __shared__ float ctx_s[D2];
    const int b = blockIdx.x;
    const int tid = threadIdx.x;
    const int lane = tid & 31, wid = tid >> 5;

    ctx_s[tid]       = g_ctx[(size_t)b * D2 + tid];
    ctx_s[tid + 512] = g_ctx[(size_t)b * D2 + tid + 512];
    __syncthreads();

    // 16 warps x 4 rows each = 64 outputs; lane-strided coalesced dot
#pragma unroll
    for (int r = 0; r < 4; r++) {
        const int o = wid * 4 + r;
        const float* wrow = W_out + (size_t)o * D2;
        float v = 0.0f;
#pragma unroll
        for (int k = 0; k < D2 / 32; k++)
            v = fmaf(ctx_s[lane + k * 32], wrow[lane + k * 32], v);
#pragma unroll
        for (int off = 16; off; off >>= 1) v += __shfl_xor_sync(0xffffffffu, v, off);
        if (lane == 0) out[(size_t)b * NOUT + o] = v + b_out[o];
    }
}

extern "C" void kernel_launch(void* const* d_in, const int* in_sizes, int n_in,
                              void* d_out, int out_size) {
    const float* x     = (const float*)d_in[0];
    const float* emb   = (const float*)d_in[1];
    const float* Wf    = (const float*)d_in[2];
    const float* bf    = (const float*)d_in[3];
    const float* Wb    = (const float*)d_in[4];
    const float* bb    = (const float*)d_in[5];
    const float* Mu    = (const float*)d_in[6];
    const float* W_out = (const float*)d_in[7];
    const float* b_out = (const float*)d_in[8];
    float* out = (float*)d_out;

    // smem: tzf 32768 + ts2 4096 + to 16384 + vvp 2048 + buf 17408 = 72704 B
    const int smem_bytes = 72704;
    static int configured = -1;
    if (configured < 0) {
        cudaFuncSetAttribute((const void*)scan_kernel,
                             cudaFuncAttributeMaxDynamicSharedMemorySize, smem_bytes);
        configured = 1;
    }

    scan_kernel<<<dim3(BB, 4), 256, smem_bytes>>>(x, emb, Wf, bf, Wb, bb, Mu);
    softmax_kernel<<<BB, 512>>>();
    ctx_kernel<<<dim3(BB, 2), 512>>>();
    out_kernel<<<BB, 512>>>(W_out, b_out, out);
}

// round 3
// speedup vs baseline: 1.9750x; 1.1099x over previous
#include <cuda_runtime.h>
#include <cuda_bf16.h>
#include <cstdint>

#define BB 128
#define TT 512
#define HH 512
#define D2 1024
#define NOUT 64
#define VN 16
#define DACT 10

// device scratch (no allocations allowed)
__device__ __nv_bfloat16 g_h[(size_t)BB * TT * D2];  // 134 MB relu(out) [b][t][d]
__device__ float g_wp[(size_t)BB * 32 * TT];         // warp logit partials [b][row][t]
__device__ float g_attn[(size_t)BB * TT];            // softmax weights
__device__ float g_ctxp[2][(size_t)BB * D2];         // context partials (2 t-halves)

__device__ __forceinline__ float fex2(float x) {
    float y; asm("ex2.approx.f32 %0, %1;" : "=f"(y) : "f"(x)); return y;
}
__device__ __forceinline__ float ftanh_a(float x) {
    float y; asm("tanh.approx.f32 %0, %1;" : "=f"(y) : "f"(x)); return y;
}
__device__ __forceinline__ float fsig_a(float x) {
    return fmaf(ftanh_a(0.5f * x), 0.5f, 0.5f);
}

// ---------------- K1: fused gate-GEMM + fo_pool scan ----------------
// block = (b, unit); unit = dir*4 + quarter; 128 threads = h in [q*128, q*128+128)
// smem (31744 B): tzf float2[VN*128] | ts2 float2[TT] | to float[VN*128] | vv uchar[TT] | buf float[4*160]
extern __shared__ float s_raw[];

__global__ void __launch_bounds__(128, 7) scan_kernel(
    const float* __restrict__ x,   // (B,T,3)
    const float* __restrict__ emb, // (16,10)
    const float* __restrict__ Wf, const float* __restrict__ bfw,
    const float* __restrict__ Wb, const float* __restrict__ bbw,
    const float* __restrict__ Mu)  // (2H,1)
{
    const int b    = blockIdx.x;
    const int unit = blockIdx.y;
    const int dir  = unit >> 2;
    const int q    = unit & 3;
    const int tid  = threadIdx.x;
    const int h    = q * 128 + tid;

    float2*        tzf = (float2*)s_raw;            // VN*128 float2 (16384 B)
    float2*        ts2 = tzf + VN * 128;            // TT float2     (4096 B)
    float*         to  = (float*)(ts2 + TT);        // VN*128        (8192 B)
    unsigned char* vv  = (unsigned char*)(to + VN * 128);  // TT     (512 B)
    float*         buf = (float*)(vv + TT);         // 4*160         (2560 B)

    const float* W    = dir ? Wb : Wf;
    const float* bias = dir ? bbw : bfw;

    // stage x row into smem
    for (int t = tid; t < TT; t += 128) {
        const float* xp = x + ((size_t)b * TT + t) * 3;
        ts2[t] = make_float2(xp[0], xp[1]);
        vv[t]  = (unsigned char)(int)xp[2];
    }

    const int ch_z = h, ch_f = HH + h, ch_o = 2 * HH + h;
    const float wz0 = W[ch_z], wz1 = W[1536 + ch_z];
    const float wf0 = W[ch_f], wf1 = W[1536 + ch_f];
    const float wo0 = W[ch_o], wo1 = W[1536 + ch_o];

    // build tables one gate at a time (keeps live regs low)
    {
        float wk[DACT];
#pragma unroll
        for (int k = 0; k < DACT; k++) wk[k] = W[(2 + k) * 1536 + ch_z];
        const float bz = bias[ch_z];
        for (int v = 0; v < VN; v++) {
            float a = bz;
#pragma unroll
            for (int k = 0; k < DACT; k++) a = fmaf(emb[v * DACT + k], wk[k], a);
            ((float*)tzf)[(v * 128 + tid) * 2] = a;
        }
#pragma unroll
        for (int k = 0; k < DACT; k++) wk[k] = W[(2 + k) * 1536 + ch_f];
        const float bfv = bias[ch_f];
        for (int v = 0; v < VN; v++) {
            float a = bfv;
#pragma unroll
            for (int k = 0; k < DACT; k++) a = fmaf(emb[v * DACT + k], wk[k], a);
            ((float*)tzf)[(v * 128 + tid) * 2 + 1] = a;
        }
#pragma unroll
        for (int k = 0; k < DACT; k++) wk[k] = W[(2 + k) * 1536 + ch_o];
        const float bo = bias[ch_o];
        for (int v = 0; v < VN; v++) {
            float a = bo;
#pragma unroll
            for (int k = 0; k < DACT; k++) a = fmaf(emb[v * DACT + k], wk[k], a);
            to[v * 128 + tid] = a;
        }
    }
    const int d = dir * HH + h;
    const float mu = Mu[d];
    __syncthreads();

    const int lane = tid & 31;
    const int wid  = tid >> 5;
    float* bufw = buf + wid * 160;                 // 32 x 5 padded tile
    const int rstep = dir ? -D2 : D2;

    float c = 0.0f;
    __nv_bfloat16* hp = g_h + ((size_t)b * TT + (dir ? TT - 1 : 0)) * D2 + d;
    float* wp_out = g_wp + ((size_t)b * 32 + unit * 4 + wid) * TT;

    for (int ch = 0; ch < TT / 4; ch++) {
#pragma unroll
        for (int j = 0; j < 4; j++) {
            const int i = ch * 4 + j;
            const int t = dir ? (TT - 1 - i) : i;
            const float2 tt = ts2[t];
            const int off = ((int)vv[t]) * 128 + tid;
            const float2 zf = tzf[off];
            const float aob = to[off];
            float az = fmaf(tt.x, wz0, fmaf(tt.y, wz1, zf.x));
            float af = fmaf(tt.x, wf0, fmaf(tt.y, wf1, zf.y));
            float ao = fmaf(tt.x, wo0, fmaf(tt.y, wo1, aob));
            float z = ftanh_a(az);
            float f = fsig_a(af);
            float o = fsig_a(ao);
            c = fmaf(f, c - z, z);                 // f*c + (1-f)*z
            float hr = fmaxf(o * c, 0.0f);
            *hp = __float2bfloat16(hr); hp += rstep;
            bufw[lane * 5 + j] = hr * mu;
        }
        __syncwarp();
        {
            const int tl = lane >> 3;              // t_local 0..3
            const int s  = lane & 7;
            float p = bufw[(s     ) * 5 + tl]
                    + bufw[(s +  8) * 5 + tl]
                    + bufw[(s + 16) * 5 + tl]
                    + bufw[(s + 24) * 5 + tl];
            p += __shfl_xor_sync(0xffffffffu, p, 4);
            p += __shfl_xor_sync(0xffffffffu, p, 2);
            p += __shfl_xor_sync(0xffffffffu, p, 1);
            if (s == 0) {
                const int i = ch * 4 + tl;
                wp_out[dir ? (TT - 1 - i) : i] = p;
            }
        }
        __syncwarp();
    }
}

// ---------------- K2: reduce warp partials -> softmax over T ----------------
__global__ void __launch_bounds__(512) softmax_kernel()
{
    __shared__ float red[16];
    const int b = blockIdx.x;
    const int t = threadIdx.x;
    const int lane = t & 31, wid = t >> 5;

    const float* wp = g_wp + (size_t)b * 32 * TT + t;
    float s = 0.0f;
#pragma unroll
    for (int uw = 0; uw < 32; uw++) s += wp[(size_t)uw * TT];

    float m = s;
#pragma unroll
    for (int o = 16; o; o >>= 1) m = fmaxf(m, __shfl_xor_sync(0xffffffffu, m, o));
    if (lane == 0) red[wid] = m;
    __syncthreads();
    if (wid == 0) {
        float v = (lane < 16) ? red[lane] : -1e30f;
#pragma unroll
        for (int o = 16; o; o >>= 1) v = fmaxf(v, __shfl_xor_sync(0xffffffffu, v, o));
        if (lane == 0) red[0] = v;
    }
    __syncthreads();
    m = red[0];
    __syncthreads();

    float e = fex2(1.4426950408889634f * (s - m));
    float su = e;
#pragma unroll
    for (int o = 16; o; o >>= 1) su += __shfl_xor_sync(0xffffffffu, su, o);
    if (lane == 0) red[wid] = su;
    __syncthreads();
    if (wid == 0) {
        float v = (lane < 16) ? red[lane] : 0.0f;
#pragma unroll
        for (int o = 16; o; o >>= 1) v += __shfl_xor_sync(0xffffffffu, v, o);
        if (lane == 0) red[0] = v;
    }
    __syncthreads();
    g_attn[(size_t)b * TT + t] = e / red[0];
}

// ---------------- K3: context partials over half the timesteps ----------------
__global__ void __launch_bounds__(512) ctx_kernel()
{
    __shared__ float a_sm[256];
    const int b  = blockIdx.x;
    const int dh = blockIdx.y;   // d half
    const int tp = blockIdx.z;   // t half
    const int tid = threadIdx.x;

    if (tid < 256) a_sm[tid] = g_attn[(size_t)b * TT + tp * 256 + tid];
    __syncthreads();

    const int d = dh * 512 + tid;
    const __nv_bfloat16* hp = g_h + ((size_t)b * TT + tp * 256) * D2 + d;
    float a0 = 0.f, a1 = 0.f, a2 = 0.f, a3 = 0.f;
    float a4 = 0.f, a5 = 0.f, a6 = 0.f, a7 = 0.f;
#pragma unroll 4
    for (int t = 0; t < 256; t += 8) {
        a0 = fmaf(a_sm[t + 0], __bfloat162float(hp[(size_t)(t + 0) * D2]), a0);
        a1 = fmaf(a_sm[t + 1], __bfloat162float(hp[(size_t)(t + 1) * D2]), a1);
        a2 = fmaf(a_sm[t + 2], __bfloat162float(hp[(size_t)(t + 2) * D2]), a2);
        a3 = fmaf(a_sm[t + 3], __bfloat162float(hp[(size_t)(t + 3) * D2]), a3);
        a4 = fmaf(a_sm[t + 4], __bfloat162float(hp[(size_t)(t + 4) * D2]), a4);
        a5 = fmaf(a_sm[t + 5], __bfloat162float(hp[(size_t)(t + 5) * D2]), a5);
        a6 = fmaf(a_sm[t + 6], __bfloat162float(hp[(size_t)(t + 6) * D2]), a6);
        a7 = fmaf(a_sm[t + 7], __bfloat162float(hp[(size_t)(t + 7) * D2]), a7);
    }
    g_ctxp[tp][(size_t)b * D2 + d] = ((a0 + a1) + (a2 + a3)) + ((a4 + a5) + (a6 + a7));
}

// ---------------- K4: relu(ctx) @ W_out^T + b_out ----------------
__global__ void __launch_bounds__(512) out_kernel(
    const float* __restrict__ W_out, const float* __restrict__ b_out,
    float* __restrict__ out)
{
    __shared__ float ctx_s[D2];
    const int b = blockIdx.x;
    const int tid = threadIdx.x;
    const int lane = tid & 31, wid = tid >> 5;

    ctx_s[tid] = fmaxf(g_ctxp[0][(size_t)b * D2 + tid] +
                       g_ctxp[1][(size_t)b * D2 + tid], 0.0f);
    ctx_s[tid + 512] = fmaxf(g_ctxp[0][(size_t)b * D2 + tid + 512] +
                             g_ctxp[1][(size_t)b * D2 + tid + 512], 0.0f);
    __syncthreads();

#pragma unroll
    for (int r = 0; r < 4; r++) {
        const int o = wid * 4 + r;
        const float* wrow = W_out + (size_t)o * D2;
        float v = 0.0f;
#pragma unroll
        for (int k = 0; k < D2 / 32; k++)
            v = fmaf(ctx_s[lane + k * 32], wrow[lane + k * 32], v);
#pragma unroll
        for (int off = 16; off; off >>= 1) v += __shfl_xor_sync(0xffffffffu, v, off);
        if (lane == 0) out[(size_t)b * NOUT + o] = v + b_out[o];
    }
}

extern "C" void kernel_launch(void* const* d_in, const int* in_sizes, int n_in,
                              void* d_out, int out_size) {
    const float* x     = (const float*)d_in[0];
    const float* emb   = (const float*)d_in[1];
    const float* Wf    = (const float*)d_in[2];
    const float* bf    = (const float*)d_in[3];
    const float* Wb    = (const float*)d_in[4];
    const float* bb    = (const float*)d_in[5];
    const float* Mu    = (const float*)d_in[6];
    const float* W_out = (const float*)d_in[7];
    const float* b_out = (const float*)d_in[8];
    float* out = (float*)d_out;

    // smem: 16384 + 4096 + 8192 + 512 + 2560 = 31744 B (< 48KB default)
    scan_kernel<<<dim3(BB, 8), 128, 31744>>>(x, emb, Wf, bf, Wb, bb, Mu);
    softmax_kernel<<<BB, 512>>>();
    ctx_kernel<<<dim3(BB, 2, 2), 512>>>();
    out_kernel<<<BB, 512>>>(W_out, b_out, out);
}